// round 7
// baseline (speedup 1.0000x reference)
#include <cuda_runtime.h>
#include <cuda_bf16.h>
#include <cstdint>

// Soft VQ encoding, fused single kernel.
// X: (b, n, 128) fp32, C: (128, 128), S: (128,)  ->  E: (b, 128, 128)
//
// Per 128-row chunk:
//   GEMM1: XC[r,k] = sum_d X[r,d]*C[k,d]    (f32x2, R8xP4 tile, SW-pipelined)
//   D[r,k] = S[k]*(X2[r] + C2[k] - 2*XC)
//   softmax over k (128) -> A[r,k]  (shared, bank-conflict-free swizzle)
//   GEMM2: E[k,d] += sum_r A[r,k]*X[r,d]    (register E, f32x2, SW-pipelined)
// Per CTA: E and Asum accumulate over all its chunks of one batch; flush via
// atomicAdd with the -Asum[k]*C[k,d] correction folded in.

#define KDIM 128
#define DDIM 128
#define CHUNK 128
#define THREADS 256
#define GRID 152

// shared layout (floats)
#define CT_STRIDE   130           // Ct[d][k], k-major pairs readable as 64-bit
#define CT_FLOATS   (128*CT_STRIDE)            // 16640
#define XS_STRIDE   132
#define XS_FLOATS   (CHUNK*XS_STRIDE)          // 16896
#define AS_FLOATS   (CHUNK*XS_STRIDE)          // 16896
#define SMEM_FLOATS (CT_FLOATS + XS_FLOATS + AS_FLOATS + 128 + 128 + 128 + 128 + 256)
#define SMEM_BYTES  (SMEM_FLOATS * 4)          // 204800

typedef unsigned long long u64;

__device__ __forceinline__ u64 pack2(float lo, float hi) {
    u64 r;
    asm("mov.b64 %0, {%1, %2};" : "=l"(r) : "f"(lo), "f"(hi));
    return r;
}
__device__ __forceinline__ void unpack2(u64 v, float& lo, float& hi) {
    asm("mov.b64 {%0, %1}, %2;" : "=f"(lo), "=f"(hi) : "l"(v));
}
__device__ __forceinline__ void ffma2(u64& acc, u64 a, u64 b) {
    asm("fma.rn.f32x2 %0, %1, %2, %0;" : "+l"(acc) : "l"(a), "l"(b));
}

// ---- GEMM1 stage helpers (R8 x P4 per-thread tile) ----
__device__ __forceinline__ void g1_ldc(u64 c[4], const u64* __restrict__ p) {
    c[0] = p[0]; c[1] = p[16]; c[2] = p[32]; c[3] = p[48];
}
__device__ __forceinline__ void g1_ldx(float x[8], const float* __restrict__ p) {
    #pragma unroll
    for (int i = 0; i < 8; ++i) x[i] = p[16 * i * XS_STRIDE];
}
__device__ __forceinline__ void g1_fma(u64 a1[8][4], const u64 c[4], const float x[8]) {
    #pragma unroll
    for (int i = 0; i < 8; ++i) {
        u64 xd = pack2(x[i], x[i]);
        ffma2(a1[i][0], xd, c[0]);
        ffma2(a1[i][1], xd, c[1]);
        ffma2(a1[i][2], xd, c[2]);
        ffma2(a1[i][3], xd, c[3]);
    }
}

// ---- GEMM2 stage helpers ----
__device__ __forceinline__ void g2_ldx(u64 x[4], const u64* __restrict__ p) {
    x[0] = p[0]; x[1] = p[16]; x[2] = p[32]; x[3] = p[48];
}
__device__ __forceinline__ void g2_lda(float a[8], const float* __restrict__ p) {
    #pragma unroll
    for (int i = 0; i < 8; ++i) a[i] = p[16 * i];
}
__device__ __forceinline__ void g2_fma(u64 accE[8][4], const u64 x[4], const float a[8]) {
    #pragma unroll
    for (int i = 0; i < 8; ++i) {
        u64 ad = pack2(a[i], a[i]);
        ffma2(accE[i][0], ad, x[0]);
        ffma2(accE[i][1], ad, x[1]);
        ffma2(accE[i][2], ad, x[2]);
        ffma2(accE[i][3], ad, x[3]);
    }
}

__global__ void __launch_bounds__(THREADS, 1)
vq_zero_kernel(float* out, int n) {
    int i = blockIdx.x * blockDim.x + threadIdx.x;
    if (i < n) out[i] = 0.0f;
}

__global__ void __launch_bounds__(THREADS, 1)
vq_encode_kernel(const float* __restrict__ Xg,
                 const float* __restrict__ Cg,
                 const float* __restrict__ Sg,
                 float* __restrict__ out,
                 int n, int b) {
    extern __shared__ float sm[];
    float* Ct    = sm;                       // [128][130]  C transposed: Ct[d*130 + k]
    float* Xs    = Ct + CT_FLOATS;           // [128][132]
    float* As    = Xs + XS_FLOATS;           // [128][132]
    float* X2s   = As + AS_FLOATS;           // [128]
    float* C2s   = X2s + 128;                // [128]
    float* Ss    = C2s + 128;                // [128]
    float* AsumS = Ss + 128;                 // [128]
    float* AsumP = AsumS + 128;              // [256] per-thread Asum partials
    const u64* Ct_u = (const u64*)Ct;        // [128][65] pair view

    const int tid = threadIdx.x;
    const int w   = tid >> 5, l = tid & 31;
    const int tr  = tid >> 4, tc = tid & 15;   // GEMM1 / GEMM2 tiling

    // ---- one-time init: transpose C, copy S, compute C2 ----
    for (int f = tid; f < KDIM * DDIM; f += THREADS) {
        int k = f >> 7, d = f & 127;
        Ct[d * CT_STRIDE + k] = Cg[f];
    }
    if (tid < KDIM) Ss[tid] = Sg[tid];
    __syncthreads();
    if (tid < KDIM) {
        float c2a = 0.f, c2b = 0.f;
        for (int d = 0; d < DDIM; d += 2) {
            float v0 = Ct[d * CT_STRIDE + tid];
            float v1 = Ct[(d + 1) * CT_STRIDE + tid];
            c2a = fmaf(v0, v0, c2a);
            c2b = fmaf(v1, v1, c2b);
        }
        C2s[tid] = c2a + c2b;
    }
    // (ordered before first use by the per-chunk __syncthreads below)

    // ---- accumulators ----
    u64 accE[8][4];                          // E[k = tr+16i][d = 2*(tc+16jp) .. +1]
    #pragma unroll
    for (int i = 0; i < 8; ++i)
        #pragma unroll
        for (int j = 0; j < 4; ++j) accE[i][j] = 0ull;
    float asum = 0.f;                        // per-thread Asum partial (half-column)

    const int ak  = tid & 127;               // Asum k index
    const int ar0 = (tid >> 7) << 6;         // Asum row range start (0 or 64)

    const int cpb   = n >> 7;                // chunks per batch
    const int total = b * cpb;
    const int g     = blockIdx.x;
    const int t0 = (int)(((long long)g       * total) / GRID);
    const int t1 = (int)(((long long)(g + 1) * total) / GRID);

    int cur_b = -1;
    for (int t = t0; t <= t1; ++t) {
        int bb = (t < t1) ? (t / cpb) : -2;  // sentinel forces final flush
        // ---- flush on batch change ----
        if (bb != cur_b) {
            if (cur_b >= 0) {
                __syncthreads();
                AsumP[tid] = asum; asum = 0.f;
                __syncthreads();
                if (tid < KDIM) AsumS[tid] = AsumP[tid] + AsumP[tid + 128];
                __syncthreads();
                #pragma unroll
                for (int i = 0; i < 8; ++i) {
                    int k = tr + 16 * i;
                    float akv = AsumS[k];
                    const float* crow = Cg + k * DDIM;
                    size_t obase = ((size_t)cur_b * KDIM + k) * DDIM;
                    #pragma unroll
                    for (int jp = 0; jp < 4; ++jp) {
                        int d0 = 2 * (tc + 16 * jp);
                        float e0, e1;
                        unpack2(accE[i][jp], e0, e1);
                        accE[i][jp] = 0ull;
                        float2 cv = *(const float2*)(crow + d0);
                        atomicAdd(&out[obase + d0],     e0 - akv * cv.x);
                        atomicAdd(&out[obase + d0 + 1], e1 - akv * cv.y);
                    }
                }
                __syncthreads();
            }
            cur_b = bb;
        }
        if (t >= t1) break;
        int c = t - cur_b * cpb;

        // ---- load X chunk (128 x 128), compute X2 per row ----
        const float* Xbase = Xg + ((size_t)cur_b * n + (size_t)c * CHUNK) * DDIM;
        #pragma unroll
        for (int it = 0; it < 16; ++it) {
            int r = w + 8 * it;              // whole warp loads one row
            float4 v = *(const float4*)(Xbase + (size_t)r * DDIM + l * 4);
            *(float4*)(Xs + r * XS_STRIDE + l * 4) = v;
            float ss = v.x * v.x + v.y * v.y + v.z * v.z + v.w * v.w;
            ss += __shfl_xor_sync(0xffffffffu, ss, 16);
            ss += __shfl_xor_sync(0xffffffffu, ss, 8);
            ss += __shfl_xor_sync(0xffffffffu, ss, 4);
            ss += __shfl_xor_sync(0xffffffffu, ss, 2);
            ss += __shfl_xor_sync(0xffffffffu, ss, 1);
            if (l == 0) X2s[r] = ss;
        }
        __syncthreads();

        // ---- GEMM1: XC (rows r = tr+16i i<8, k-pairs p = tc+16jp jp<4) ----
        // Software-pipelined: double-buffered c/x stages, >=32-instr gap
        // between every LDS and its consumer.
        {
            u64 a1[8][4];
            #pragma unroll
            for (int i = 0; i < 8; ++i)
                #pragma unroll
                for (int j = 0; j < 4; ++j) a1[i][j] = 0ull;

            const float* xsb = Xs + tr * XS_STRIDE;
            const u64*   ctp = Ct_u + tc;

            u64 cA[4], cB[4];
            float xA[8], xB[8];
            g1_ldc(cA, ctp);                       // dd = 0
            g1_ldx(xA, xsb);
            g1_ldc(cB, ctp + (CT_STRIDE / 2));     // dd = 1
            g1_ldx(xB, xsb + 1);

            #pragma unroll 1
            for (int dd = 0; dd < DDIM - 2; dd += 2) {
                g1_fma(a1, cA, xA);
                g1_ldc(cA, ctp + (dd + 2) * (CT_STRIDE / 2));
                g1_ldx(xA, xsb + (dd + 2));
                g1_fma(a1, cB, xB);
                g1_ldc(cB, ctp + (dd + 3) * (CT_STRIDE / 2));
                g1_ldx(xB, xsb + (dd + 3));
            }
            g1_fma(a1, cA, xA);                    // dd = 126
            g1_fma(a1, cB, xB);                    // dd = 127

            // D = S[k]*(X2[r] + C2[k] - 2*XC) -> As
            #pragma unroll
            for (int i = 0; i < 8; ++i) {
                int r = tr + 16 * i;
                float x2 = X2s[r];
                #pragma unroll
                for (int jp = 0; jp < 4; ++jp) {
                    float lo, hi;
                    unpack2(a1[i][jp], lo, hi);
                    int k0 = 2 * (tc + 16 * jp);
                    float d0 = Ss[k0]     * (x2 + C2s[k0]     - 2.f * lo);
                    float d1 = Ss[k0 + 1] * (x2 + C2s[k0 + 1] - 2.f * hi);
                    *(float2*)(As + r * XS_STRIDE + k0) = make_float2(d0, d1);
                }
            }
        }
        __syncthreads();

        // ---- softmax over k: 4 threads per row, 32 k each, 2 row-halves ----
        // Swizzled element order within each 32-wide segment makes the 32
        // lanes of a warp (8 rows x 4 segs) hit 32 distinct banks.
        #pragma unroll
        for (int h = 0; h < 2; ++h) {
            int r = (tid >> 2) + (h << 6), q = tid & 3;
            float* row = As + r * XS_STRIDE + q * 32;
            const int rot = (8 * q + r) & 31;
            float v[32];
            float m = -3.4e38f;
            #pragma unroll
            for (int j = 0; j < 32; ++j) {
                v[j] = row[(j + rot) & 31];
                m = fmaxf(m, v[j]);
            }
            m = fmaxf(m, __shfl_xor_sync(0xffffffffu, m, 1));
            m = fmaxf(m, __shfl_xor_sync(0xffffffffu, m, 2));
            float s0 = 0.f, s1 = 0.f;
            #pragma unroll
            for (int j = 0; j < 32; j += 2) {
                v[j]     = __expf(v[j]     - m);
                v[j + 1] = __expf(v[j + 1] - m);
                s0 += v[j]; s1 += v[j + 1];
            }
            float s = s0 + s1;
            s += __shfl_xor_sync(0xffffffffu, s, 1);
            s += __shfl_xor_sync(0xffffffffu, s, 2);
            float inv = __frcp_rn(s);
            #pragma unroll
            for (int j = 0; j < 32; ++j) row[(j + rot) & 31] = v[j] * inv;
        }
        __syncthreads();

        // ---- Asum[k] partial: all 256 threads, 64 rows each ----
        {
            const float* col = As + ar0 * XS_STRIDE + ak;
            float a0 = 0.f, a1s = 0.f, a2 = 0.f, a3 = 0.f;
            #pragma unroll 4
            for (int rr = 0; rr < 64; rr += 4) {
                a0  += col[(rr    ) * XS_STRIDE];
                a1s += col[(rr + 1) * XS_STRIDE];
                a2  += col[(rr + 2) * XS_STRIDE];
                a3  += col[(rr + 3) * XS_STRIDE];
            }
            asum += (a0 + a1s) + (a2 + a3);
        }

        // ---- GEMM2: E[k,d] += A[n,k]*X[n,d]  (software-pipelined) ----
        {
            const u64*   Xs_u = (const u64*)Xs;
            const u64*   xp   = Xs_u + tc;
            const float* ap   = As + tr;

            u64 xA[4], xB[4];
            float aA[8], aB[8];
            g2_ldx(xA, xp);                        // nn = 0
            g2_lda(aA, ap);
            g2_ldx(xB, xp + (XS_STRIDE / 2));      // nn = 1
            g2_lda(aB, ap + XS_STRIDE);

            #pragma unroll 1
            for (int nn = 0; nn < CHUNK - 2; nn += 2) {
                g2_fma(accE, xA, aA);
                g2_ldx(xA, xp + (nn + 2) * (XS_STRIDE / 2));
                g2_lda(aA, ap + (nn + 2) * XS_STRIDE);
                g2_fma(accE, xB, aB);
                g2_ldx(xB, xp + (nn + 3) * (XS_STRIDE / 2));
                g2_lda(aB, ap + (nn + 3) * XS_STRIDE);
            }
            g2_fma(accE, xA, aA);                  // nn = 126
            g2_fma(accE, xB, aB);                  // nn = 127
        }
        __syncthreads();   // before next chunk overwrites Xs/As
    }
}

extern "C" void kernel_launch(void* const* d_in, const int* in_sizes, int n_in,
                              void* d_out, int out_size) {
    (void)n_in;
    const float* X = (const float*)d_in[0];
    const float* C = (const float*)d_in[1];
    const float* S = (const float*)d_in[2];
    float* out = (float*)d_out;

    int b = out_size / (KDIM * DDIM);            // 8
    if (b < 1) b = 1;
    long long rows = (long long)in_sizes[0] / DDIM;   // b*n
    int n = (int)(rows / b);                     // 16384

    cudaFuncSetAttribute(vq_encode_kernel,
                         cudaFuncAttributeMaxDynamicSharedMemorySize, SMEM_BYTES);

    int zgrid = (out_size + THREADS - 1) / THREADS;
    vq_zero_kernel<<<zgrid, THREADS>>>(out, out_size);
    vq_encode_kernel<<<GRID, THREADS, SMEM_BYTES>>>(X, C, S, out, n, b);
}

// round 15
// speedup vs baseline: 2.1206x; 2.1206x over previous
#include <cuda_runtime.h>
#include <cuda_bf16.h>
#include <cstdint>

// Soft VQ encoding via warp-level bf16 MMA (mma.sync m16n8k16, base-target PTX).
// X:(b,n,128) f32, C:(128,128), S:(128,) -> E:(b,128,128)
// Per 128-row chunk:
//   GEMM1 D[n,k] = X·C^T      3 split-bf16 passes, f32 acc in regs
//   softmax over k in the acc register layout (4-lane shfl groups)
//   A -> bf16 hi/lo tiles in smem (conflict-free STS)
//   GEMM2 E[k,d] += A^T·X     3 passes, A^T & X via ldmatrix.trans
//   Asum via shfl-reduce of float(Ah)+float(Al) into per-warp smem slices
// E lives in registers across a batch; flush = atomicAdd(E - Asum*C).

#define KDIM 128
#define DDIM 128
#define THREADS 256
#define GRID 152

#define STR  136            // bf16 elements per tile row
#define ROWB 272            // bytes per tile row
#define TILE_B (128*ROWB)   // 34816

#define OFF_XH 0u
#define OFF_XL 34816u
#define OFF_AH 69632u
#define OFF_AL 104448u
#define OFF_CH 139264u
#define OFF_CL 174080u
#define OFF_X2 208896u      // 128 f32
#define OFF_C2 209408u
#define OFF_S  209920u
#define OFF_AW 210432u      // AsumW[8][128] f32
#define SMEM_BYTES 214528u

typedef unsigned long long u64;

static __device__ __forceinline__ uint32_t s2u(const void* p) {
    uint32_t a;
    asm("{ .reg .u64 t; cvta.to.shared.u64 t, %1; cvt.u32.u64 %0, t; }" : "=r"(a) : "l"(p));
    return a;
}
static __device__ __forceinline__ void ldsm4(uint32_t& r0, uint32_t& r1, uint32_t& r2,
                                             uint32_t& r3, uint32_t a) {
    asm volatile("ldmatrix.sync.aligned.m8n8.x4.shared.b16 {%0,%1,%2,%3}, [%4];"
                 : "=r"(r0), "=r"(r1), "=r"(r2), "=r"(r3) : "r"(a));
}
static __device__ __forceinline__ void ldsm4t(uint32_t& r0, uint32_t& r1, uint32_t& r2,
                                              uint32_t& r3, uint32_t a) {
    asm volatile("ldmatrix.sync.aligned.m8n8.x4.trans.shared.b16 {%0,%1,%2,%3}, [%4];"
                 : "=r"(r0), "=r"(r1), "=r"(r2), "=r"(r3) : "r"(a));
}
static __device__ __forceinline__ void mma16816(float c[4], uint32_t a0, uint32_t a1,
                                                uint32_t a2, uint32_t a3,
                                                uint32_t b0, uint32_t b1) {
    asm volatile("mma.sync.aligned.m16n8k16.row.col.f32.bf16.bf16.f32 "
                 "{%0,%1,%2,%3}, {%4,%5,%6,%7}, {%8,%9}, {%0,%1,%2,%3};"
                 : "+f"(c[0]), "+f"(c[1]), "+f"(c[2]), "+f"(c[3])
                 : "r"(a0), "r"(a1), "r"(a2), "r"(a3), "r"(b0), "r"(b1));
}

// split one float4 into packed bf16 hi/lo u64s
static __device__ __forceinline__ void split4(float4 v, u64& hp, u64& lp) {
    __nv_bfloat16 h0 = __float2bfloat16_rn(v.x), h1 = __float2bfloat16_rn(v.y);
    __nv_bfloat16 h2 = __float2bfloat16_rn(v.z), h3 = __float2bfloat16_rn(v.w);
    __nv_bfloat16 g0 = __float2bfloat16_rn(v.x - __bfloat162float(h0));
    __nv_bfloat16 g1 = __float2bfloat16_rn(v.y - __bfloat162float(h1));
    __nv_bfloat16 g2 = __float2bfloat16_rn(v.z - __bfloat162float(h2));
    __nv_bfloat16 g3 = __float2bfloat16_rn(v.w - __bfloat162float(h3));
    hp = (u64)__bfloat16_as_ushort(h0) | ((u64)__bfloat16_as_ushort(h1) << 16)
       | ((u64)__bfloat16_as_ushort(h2) << 32) | ((u64)__bfloat16_as_ushort(h3) << 48);
    lp = (u64)__bfloat16_as_ushort(g0) | ((u64)__bfloat16_as_ushort(g1) << 16)
       | ((u64)__bfloat16_as_ushort(g2) << 32) | ((u64)__bfloat16_as_ushort(g3) << 48);
}

__global__ void __launch_bounds__(THREADS, 1)
vq_zero_kernel(float* out, int n) {
    int i = blockIdx.x * blockDim.x + threadIdx.x;
    if (i < n) out[i] = 0.0f;
}

__global__ void __launch_bounds__(THREADS, 1)
vq_encode_kernel(const float* __restrict__ Xg,
                 const float* __restrict__ Cg,
                 const float* __restrict__ Sg,
                 float* __restrict__ out,
                 int nseq, int b) {
    extern __shared__ char smc[];
    const uint32_t sb = s2u(smc);

    const int tid = threadIdx.x;
    const int w = tid >> 5, l = tid & 31;
    const int g = l >> 2, tq = l & 3;

    float* X2s = (float*)(smc + OFF_X2);
    float* C2s = (float*)(smc + OFF_C2);
    float* Ssm = (float*)(smc + OFF_S);
    float* AW  = (float*)(smc + OFF_AW);

    // ---- init: C hi/lo tiles, C2, S; zero AsumW ----
    #pragma unroll
    for (int it = 0; it < 16; ++it) {
        int r = w + 8 * it;
        float4 v = *(const float4*)(Cg + (size_t)r * DDIM + 4 * l);
        u64 hp, lp; split4(v, hp, lp);
        *(u64*)(smc + OFF_CH + r * ROWB + 8 * l) = hp;
        *(u64*)(smc + OFF_CL + r * ROWB + 8 * l) = lp;
        float ss = v.x*v.x + v.y*v.y + v.z*v.z + v.w*v.w;
        ss += __shfl_xor_sync(~0u, ss, 16); ss += __shfl_xor_sync(~0u, ss, 8);
        ss += __shfl_xor_sync(~0u, ss, 4);  ss += __shfl_xor_sync(~0u, ss, 2);
        ss += __shfl_xor_sync(~0u, ss, 1);
        if (l == 0) C2s[r] = ss;
    }
    if (tid < KDIM) Ssm[tid] = Sg[tid];
    for (int i = tid; i < 1024; i += THREADS) AW[i] = 0.f;

    // ---- ldmatrix per-lane byte offsets ----
    const uint32_t l7 = l & 7, lb3 = (l >> 3) & 1, lb4 = (l >> 4) & 1;
    // GEMM1 A (X, non-trans): rows 16w+(l&15), col +16B for lanes>=16
    const uint32_t a1off = (uint32_t)(16 * w + (l & 15)) * ROWB + (lb4 << 4);
    // GEMM1 B (C, non-trans): rows l7+8*lb4 (+16*tp), col +16B for lb3
    const uint32_t b1off = (l7 + 8 * lb4) * ROWB + (lb3 << 4);
    // GEMM2 A (A tile, trans): rows l7+8*lb4 (+16*s), col 32w (+16B for lb3)
    const uint32_t a2off = (l7 + 8 * lb4) * ROWB + 32 * (uint32_t)w + (lb3 << 4);
    // GEMM2 B (X, trans): rows l7+8*lb3 (+16*s), col +16B for lb4 (+32*tp)
    const uint32_t b2off = (l7 + 8 * lb3) * ROWB + (lb4 << 4);

    // ---- persistent accumulators ----
    float Eacc[16][4];
    #pragma unroll
    for (int i = 0; i < 16; ++i)
        #pragma unroll
        for (int j = 0; j < 4; ++j) Eacc[i][j] = 0.f;

    const int cpb   = nseq >> 7;
    const int total = b * cpb;
    const int gb = blockIdx.x;
    const int t0 = (int)(((long long)gb       * total) / GRID);
    const int t1 = (int)(((long long)(gb + 1) * total) / GRID);

    int cur_b = -1;
    for (int t = t0; t <= t1; ++t) {
        int bb = (t < t1) ? (t / cpb) : -2;
        if (bb != cur_b) {
            if (cur_b >= 0) {
                // ---- flush batch cur_b ----
                __syncthreads();
                int k0 = 16 * w + g, k1 = k0 + 8;
                float as0 = 0.f, as1 = 0.f;
                #pragma unroll
                for (int w2 = 0; w2 < 8; ++w2) {
                    as0 += AW[w2 * 128 + k0];
                    as1 += AW[w2 * 128 + k1];
                }
                #pragma unroll
                for (int ti = 0; ti < 16; ++ti) {
                    int d0 = 8 * ti + 2 * tq;
                    size_t o0 = ((size_t)cur_b * KDIM + k0) * DDIM + d0;
                    size_t o1 = ((size_t)cur_b * KDIM + k1) * DDIM + d0;
                    atomicAdd(&out[o0],     Eacc[ti][0] - as0 * __ldg(&Cg[k0 * DDIM + d0]));
                    atomicAdd(&out[o0 + 1], Eacc[ti][1] - as0 * __ldg(&Cg[k0 * DDIM + d0 + 1]));
                    atomicAdd(&out[o1],     Eacc[ti][2] - as1 * __ldg(&Cg[k1 * DDIM + d0]));
                    atomicAdd(&out[o1 + 1], Eacc[ti][3] - as1 * __ldg(&Cg[k1 * DDIM + d0 + 1]));
                    Eacc[ti][0] = Eacc[ti][1] = Eacc[ti][2] = Eacc[ti][3] = 0.f;
                }
                __syncthreads();
                for (int i = tid; i < 1024; i += THREADS) AW[i] = 0.f;
            }
            cur_b = bb;
        }
        if (t >= t1) break;
        int c = t - cur_b * cpb;

        __syncthreads();   // prev GEMM2 done reading Xh/Xl/A tiles

        // ---- load X chunk -> bf16 hi/lo tiles + X2 ----
        const float* Xb = Xg + ((size_t)cur_b * nseq + (size_t)c * 128) * DDIM;
        #pragma unroll
        for (int it = 0; it < 16; ++it) {
            int r = w + 8 * it;
            float4 v = *(const float4*)(Xb + (size_t)r * DDIM + 4 * l);
            u64 hp, lp; split4(v, hp, lp);
            *(u64*)(smc + OFF_XH + r * ROWB + 8 * l) = hp;
            *(u64*)(smc + OFF_XL + r * ROWB + 8 * l) = lp;
            float ss = v.x*v.x + v.y*v.y + v.z*v.z + v.w*v.w;
            ss += __shfl_xor_sync(~0u, ss, 16); ss += __shfl_xor_sync(~0u, ss, 8);
            ss += __shfl_xor_sync(~0u, ss, 4);  ss += __shfl_xor_sync(~0u, ss, 2);
            ss += __shfl_xor_sync(~0u, ss, 1);
            if (l == 0) X2s[r] = ss;
        }
        __syncthreads();

        // ---- GEMM1: D = X·C^T, 3 split passes ----
        float dacc[16][4];
        #pragma unroll
        for (int i = 0; i < 16; ++i)
            #pragma unroll
            for (int j = 0; j < 4; ++j) dacc[i][j] = 0.f;

        #pragma unroll 1
        for (int ps = 0; ps < 3; ++ps) {
            uint32_t ab = sb + (ps == 1 ? OFF_XL : OFF_XH) + a1off;
            uint32_t cb = sb + (ps == 2 ? OFF_CL : OFF_CH) + b1off;
            #pragma unroll 1
            for (int s = 0; s < 8; ++s) {
                uint32_t x0, x1, x2, x3;
                ldsm4(x0, x1, x2, x3, ab + 32u * s);
                #pragma unroll
                for (int tp = 0; tp < 8; ++tp) {
                    uint32_t c0, c1, c2, c3;
                    ldsm4(c0, c1, c2, c3, cb + (uint32_t)tp * (16u * ROWB) + 32u * s);
                    mma16816(dacc[2 * tp],     x0, x1, x2, x3, c0, c1);
                    mma16816(dacc[2 * tp + 1], x0, x1, x2, x3, c2, c3);
                }
            }
        }

        // ---- softmax in register layout ----
        {
            int row0 = 16 * w + g;
            float x20 = X2s[row0], x21 = X2s[row0 + 8];
            float m0 = -3.4e38f, m1 = -3.4e38f;
            #pragma unroll
            for (int ti = 0; ti < 16; ++ti) {
                int k = 8 * ti + 2 * tq;
                float s0 = Ssm[k], s1 = Ssm[k + 1];
                float c20 = C2s[k], c21 = C2s[k + 1];
                dacc[ti][0] = s0 * (x20 + c20 - 2.f * dacc[ti][0]);
                dacc[ti][1] = s1 * (x20 + c21 - 2.f * dacc[ti][1]);
                dacc[ti][2] = s0 * (x21 + c20 - 2.f * dacc[ti][2]);
                dacc[ti][3] = s1 * (x21 + c21 - 2.f * dacc[ti][3]);
                m0 = fmaxf(m0, fmaxf(dacc[ti][0], dacc[ti][1]));
                m1 = fmaxf(m1, fmaxf(dacc[ti][2], dacc[ti][3]));
            }
            m0 = fmaxf(m0, __shfl_xor_sync(~0u, m0, 1));
            m0 = fmaxf(m0, __shfl_xor_sync(~0u, m0, 2));
            m1 = fmaxf(m1, __shfl_xor_sync(~0u, m1, 1));
            m1 = fmaxf(m1, __shfl_xor_sync(~0u, m1, 2));
            float sm0 = 0.f, sm1 = 0.f;
            #pragma unroll
            for (int ti = 0; ti < 16; ++ti) {
                dacc[ti][0] = __expf(dacc[ti][0] - m0);
                dacc[ti][1] = __expf(dacc[ti][1] - m0);
                dacc[ti][2] = __expf(dacc[ti][2] - m1);
                dacc[ti][3] = __expf(dacc[ti][3] - m1);
                sm0 += dacc[ti][0] + dacc[ti][1];
                sm1 += dacc[ti][2] + dacc[ti][3];
            }
            sm0 += __shfl_xor_sync(~0u, sm0, 1);
            sm0 += __shfl_xor_sync(~0u, sm0, 2);
            sm1 += __shfl_xor_sync(~0u, sm1, 1);
            sm1 += __shfl_xor_sync(~0u, sm1, 2);
            float inv0 = __frcp_rn(sm0), inv1 = __frcp_rn(sm1);

            // A hi/lo STS + Asum partials (reduced per-ti to cap registers)
            uint32_t arow0 = (uint32_t)row0 * ROWB + 4u * tq;
            uint32_t arow1 = arow0 + 8u * ROWB;
            float* aw = AW + w * 128;
            #pragma unroll
            for (int ti = 0; ti < 16; ++ti) {
                float a00 = dacc[ti][0] * inv0, a01 = dacc[ti][1] * inv0;
                float a10 = dacc[ti][2] * inv1, a11 = dacc[ti][3] * inv1;
                __nv_bfloat16 h00 = __float2bfloat16_rn(a00), h01 = __float2bfloat16_rn(a01);
                __nv_bfloat16 h10 = __float2bfloat16_rn(a10), h11 = __float2bfloat16_rn(a11);
                float f00 = __bfloat162float(h00), f01 = __bfloat162float(h01);
                float f10 = __bfloat162float(h10), f11 = __bfloat162float(h11);
                __nv_bfloat16 g00 = __float2bfloat16_rn(a00 - f00);
                __nv_bfloat16 g01 = __float2bfloat16_rn(a01 - f01);
                __nv_bfloat16 g10 = __float2bfloat16_rn(a10 - f10);
                __nv_bfloat16 g11 = __float2bfloat16_rn(a11 - f11);
                uint32_t hi0 = (uint32_t)__bfloat16_as_ushort(h00) | ((uint32_t)__bfloat16_as_ushort(h01) << 16);
                uint32_t hi1 = (uint32_t)__bfloat16_as_ushort(h10) | ((uint32_t)__bfloat16_as_ushort(h11) << 16);
                uint32_t lo0 = (uint32_t)__bfloat16_as_ushort(g00) | ((uint32_t)__bfloat16_as_ushort(g01) << 16);
                uint32_t lo1 = (uint32_t)__bfloat16_as_ushort(g10) | ((uint32_t)__bfloat16_as_ushort(g11) << 16);
                uint32_t cb2 = 16u * ti;
                *(uint32_t*)(smc + OFF_AH + arow0 + cb2) = hi0;
                *(uint32_t*)(smc + OFF_AH + arow1 + cb2) = hi1;
                *(uint32_t*)(smc + OFF_AL + arow0 + cb2) = lo0;
                *(uint32_t*)(smc + OFF_AL + arow1 + cb2) = lo1;
                // asum partial for cols 8ti+2tq, +1 (effective A = hi+lo)
                float av0 = (f00 + __bfloat162float(g00)) + (f10 + __bfloat162float(g10));
                float av1 = (f01 + __bfloat162float(g01)) + (f11 + __bfloat162float(g11));
                av0 += __shfl_xor_sync(~0u, av0, 4);
                av0 += __shfl_xor_sync(~0u, av0, 8);
                av0 += __shfl_xor_sync(~0u, av0, 16);
                av1 += __shfl_xor_sync(~0u, av1, 4);
                av1 += __shfl_xor_sync(~0u, av1, 8);
                av1 += __shfl_xor_sync(~0u, av1, 16);
                if (l < 4) {
                    aw[8 * ti + 2 * tq]     += av0;
                    aw[8 * ti + 2 * tq + 1] += av1;
                }
            }
        }
        __syncthreads();   // A tiles complete

        // ---- GEMM2: E += A^T·X, 3 split passes (trans frags) ----
        #pragma unroll 1
        for (int ps = 0; ps < 3; ++ps) {
            uint32_t ab = sb + (ps == 1 ? OFF_AL : OFF_AH) + a2off;
            uint32_t xb = sb + (ps == 2 ? OFF_XL : OFF_XH) + b2off;
            #pragma unroll 1
            for (int s = 0; s < 8; ++s) {
                uint32_t a0, a1, a2, a3;
                ldsm4t(a0, a1, a2, a3, ab + (uint32_t)s * (16u * ROWB));
                #pragma unroll
                for (int tp = 0; tp < 8; ++tp) {
                    uint32_t b0, b1, b2, b3;
                    ldsm4t(b0, b1, b2, b3, xb + (uint32_t)s * (16u * ROWB) + 32u * tp);
                    mma16816(Eacc[2 * tp],     a0, a1, a2, a3, b0, b1);
                    mma16816(Eacc[2 * tp + 1], a0, a1, a2, a3, b2, b3);
                }
            }
        }
    }
}

extern "C" void kernel_launch(void* const* d_in, const int* in_sizes, int n_in,
                              void* d_out, int out_size) {
    (void)n_in;
    const float* X = (const float*)d_in[0];
    const float* C = (const float*)d_in[1];
    const float* S = (const float*)d_in[2];
    float* out = (float*)d_out;

    int b = out_size / (KDIM * DDIM);
    if (b < 1) b = 1;
    long long rows = (long long)in_sizes[0] / DDIM;
    int n = (int)(rows / b);

    cudaFuncSetAttribute(vq_encode_kernel,
                         cudaFuncAttributeMaxDynamicSharedMemorySize, SMEM_BYTES);

    int zgrid = (out_size + THREADS - 1) / THREADS;
    vq_zero_kernel<<<zgrid, THREADS>>>(out, out_size);
    vq_encode_kernel<<<GRID, THREADS, SMEM_BYTES>>>(X, C, S, out, n, b);
}

// round 17
// speedup vs baseline: 2.2678x; 1.0694x over previous
#include <cuda_runtime.h>
#include <cuda_bf16.h>
#include <cstdint>

// Soft VQ encoding via warp-level bf16 MMA (mma.sync m16n8k16, base-target PTX).
// X:(b,n,128) f32, C:(128,128), S:(128,) -> E:(b,128,128)
// Per 128-row chunk:
//   GEMM1 D[n,k] = X·C^T      split-bf16 (Xh·Ch + Xl·Ch + Xh·Cl), fused sweep
//   softmax over k in the acc register layout (4-lane shfl groups)
//   A -> bf16 hi/lo tiles in smem (conflict-free STS)
//   GEMM2 E[k,d] += A^T·X     (Ah·Xh + Al·Xh + Ah·Xl), fused sweep, trans frags
//   Asum via shfl-reduce of float(Ah)+float(Al) into per-warp smem slices
// E lives in registers across a batch; flush = atomicAdd(E - Asum*C).

#define KDIM 128
#define DDIM 128
#define THREADS 256
#define GRID 152

#define STR  136            // bf16 elements per tile row
#define ROWB 272            // bytes per tile row
#define TILE_B (128*ROWB)   // 34816

#define OFF_XH 0u
#define OFF_XL 34816u
#define OFF_AH 69632u
#define OFF_AL 104448u
#define OFF_CH 139264u
#define OFF_CL 174080u
#define OFF_X2 208896u      // 128 f32
#define OFF_C2 209408u
#define OFF_S  209920u
#define OFF_AW 210432u      // AsumW[8][128] f32
#define SMEM_BYTES 214528u

typedef unsigned long long u64;

static __device__ __forceinline__ uint32_t s2u(const void* p) {
    uint32_t a;
    asm("{ .reg .u64 t; cvta.to.shared.u64 t, %1; cvt.u32.u64 %0, t; }" : "=r"(a) : "l"(p));
    return a;
}
static __device__ __forceinline__ void ldsm4(uint32_t& r0, uint32_t& r1, uint32_t& r2,
                                             uint32_t& r3, uint32_t a) {
    asm volatile("ldmatrix.sync.aligned.m8n8.x4.shared.b16 {%0,%1,%2,%3}, [%4];"
                 : "=r"(r0), "=r"(r1), "=r"(r2), "=r"(r3) : "r"(a));
}
static __device__ __forceinline__ void ldsm4t(uint32_t& r0, uint32_t& r1, uint32_t& r2,
                                              uint32_t& r3, uint32_t a) {
    asm volatile("ldmatrix.sync.aligned.m8n8.x4.trans.shared.b16 {%0,%1,%2,%3}, [%4];"
                 : "=r"(r0), "=r"(r1), "=r"(r2), "=r"(r3) : "r"(a));
}
static __device__ __forceinline__ void mma16816(float c[4], uint32_t a0, uint32_t a1,
                                                uint32_t a2, uint32_t a3,
                                                uint32_t b0, uint32_t b1) {
    asm volatile("mma.sync.aligned.m16n8k16.row.col.f32.bf16.bf16.f32 "
                 "{%0,%1,%2,%3}, {%4,%5,%6,%7}, {%8,%9}, {%0,%1,%2,%3};"
                 : "+f"(c[0]), "+f"(c[1]), "+f"(c[2]), "+f"(c[3])
                 : "r"(a0), "r"(a1), "r"(a2), "r"(a3), "r"(b0), "r"(b1));
}

// split one float4 into packed bf16 hi/lo u64s
static __device__ __forceinline__ void split4(float4 v, u64& hp, u64& lp) {
    __nv_bfloat16 h0 = __float2bfloat16_rn(v.x), h1 = __float2bfloat16_rn(v.y);
    __nv_bfloat16 h2 = __float2bfloat16_rn(v.z), h3 = __float2bfloat16_rn(v.w);
    __nv_bfloat16 g0 = __float2bfloat16_rn(v.x - __bfloat162float(h0));
    __nv_bfloat16 g1 = __float2bfloat16_rn(v.y - __bfloat162float(h1));
    __nv_bfloat16 g2 = __float2bfloat16_rn(v.z - __bfloat162float(h2));
    __nv_bfloat16 g3 = __float2bfloat16_rn(v.w - __bfloat162float(h3));
    hp = (u64)__bfloat16_as_ushort(h0) | ((u64)__bfloat16_as_ushort(h1) << 16)
       | ((u64)__bfloat16_as_ushort(h2) << 32) | ((u64)__bfloat16_as_ushort(h3) << 48);
    lp = (u64)__bfloat16_as_ushort(g0) | ((u64)__bfloat16_as_ushort(g1) << 16)
       | ((u64)__bfloat16_as_ushort(g2) << 32) | ((u64)__bfloat16_as_ushort(g3) << 48);
}

__global__ void __launch_bounds__(THREADS, 1)
vq_zero_kernel(float* out, int n) {
    int i = blockIdx.x * blockDim.x + threadIdx.x;
    if (i < n) out[i] = 0.0f;
}

__global__ void __launch_bounds__(THREADS, 1)
vq_encode_kernel(const float* __restrict__ Xg,
                 const float* __restrict__ Cg,
                 const float* __restrict__ Sg,
                 float* __restrict__ out,
                 int nseq, int b) {
    extern __shared__ char smc[];
    const uint32_t sb = s2u(smc);

    const int tid = threadIdx.x;
    const int w = tid >> 5, l = tid & 31;
    const int g = l >> 2, tq = l & 3;

    float* X2s = (float*)(smc + OFF_X2);
    float* C2s = (float*)(smc + OFF_C2);
    float* Ssm = (float*)(smc + OFF_S);
    float* AW  = (float*)(smc + OFF_AW);

    // ---- init: C hi/lo tiles, C2, S; zero AsumW ----
    #pragma unroll
    for (int it = 0; it < 16; ++it) {
        int r = w + 8 * it;
        float4 v = *(const float4*)(Cg + (size_t)r * DDIM + 4 * l);
        u64 hp, lp; split4(v, hp, lp);
        *(u64*)(smc + OFF_CH + r * ROWB + 8 * l) = hp;
        *(u64*)(smc + OFF_CL + r * ROWB + 8 * l) = lp;
        float ss = v.x*v.x + v.y*v.y + v.z*v.z + v.w*v.w;
        ss += __shfl_xor_sync(~0u, ss, 16); ss += __shfl_xor_sync(~0u, ss, 8);
        ss += __shfl_xor_sync(~0u, ss, 4);  ss += __shfl_xor_sync(~0u, ss, 2);
        ss += __shfl_xor_sync(~0u, ss, 1);
        if (l == 0) C2s[r] = ss;
    }
    if (tid < KDIM) Ssm[tid] = Sg[tid];
    for (int i = tid; i < 1024; i += THREADS) AW[i] = 0.f;

    // ---- ldmatrix per-lane byte offsets ----
    const uint32_t l7 = l & 7, lb3 = (l >> 3) & 1, lb4 = (l >> 4) & 1;
    // GEMM1 A (X, non-trans): rows 16w+(l&15), col +16B for lanes>=16
    const uint32_t a1off = (uint32_t)(16 * w + (l & 15)) * ROWB + (lb4 << 4);
    // GEMM1 B (C, non-trans): rows l7+8*lb4 (+16*tp), col +16B for lb3
    const uint32_t b1off = (l7 + 8 * lb4) * ROWB + (lb3 << 4);
    // GEMM2 A (A tile, trans): rows l7+8*lb4 (+16*s), col 32w (+16B for lb3)
    const uint32_t a2off = (l7 + 8 * lb4) * ROWB + 32 * (uint32_t)w + (lb3 << 4);
    // GEMM2 B (X, trans): rows l7+8*lb3 (+16*s), col +16B for lb4 (+32*tp)
    const uint32_t b2off = (l7 + 8 * lb3) * ROWB + (lb4 << 4);

    // ---- persistent accumulators ----
    float Eacc[16][4];
    #pragma unroll
    for (int i = 0; i < 16; ++i)
        #pragma unroll
        for (int j = 0; j < 4; ++j) Eacc[i][j] = 0.f;

    const int cpb   = nseq >> 7;
    const int total = b * cpb;
    const int gb = blockIdx.x;
    const int t0 = (int)(((long long)gb       * total) / GRID);
    const int t1 = (int)(((long long)(gb + 1) * total) / GRID);

    int cur_b = -1;
    for (int t = t0; t <= t1; ++t) {
        int bb = (t < t1) ? (t / cpb) : -2;
        if (bb != cur_b) {
            if (cur_b >= 0) {
                // ---- flush batch cur_b ----
                __syncthreads();
                int k0 = 16 * w + g, k1 = k0 + 8;
                float as0 = 0.f, as1 = 0.f;
                #pragma unroll
                for (int w2 = 0; w2 < 8; ++w2) {
                    as0 += AW[w2 * 128 + k0];
                    as1 += AW[w2 * 128 + k1];
                }
                #pragma unroll
                for (int ti = 0; ti < 16; ++ti) {
                    int d0 = 8 * ti + 2 * tq;
                    size_t o0 = ((size_t)cur_b * KDIM + k0) * DDIM + d0;
                    size_t o1 = ((size_t)cur_b * KDIM + k1) * DDIM + d0;
                    atomicAdd(&out[o0],     Eacc[ti][0] - as0 * __ldg(&Cg[k0 * DDIM + d0]));
                    atomicAdd(&out[o0 + 1], Eacc[ti][1] - as0 * __ldg(&Cg[k0 * DDIM + d0 + 1]));
                    atomicAdd(&out[o1],     Eacc[ti][2] - as1 * __ldg(&Cg[k1 * DDIM + d0]));
                    atomicAdd(&out[o1 + 1], Eacc[ti][3] - as1 * __ldg(&Cg[k1 * DDIM + d0 + 1]));
                    Eacc[ti][0] = Eacc[ti][1] = Eacc[ti][2] = Eacc[ti][3] = 0.f;
                }
                __syncthreads();
                for (int i = tid; i < 1024; i += THREADS) AW[i] = 0.f;
            }
            cur_b = bb;
        }
        if (t >= t1) break;
        int c = t - cur_b * cpb;

        __syncthreads();   // prev GEMM2 done reading Xh/Xl/A tiles

        // ---- load X chunk -> bf16 hi/lo tiles + X2 ----
        const float* Xb = Xg + ((size_t)cur_b * nseq + (size_t)c * 128) * DDIM;
        #pragma unroll
        for (int it = 0; it < 16; ++it) {
            int r = w + 8 * it;
            float4 v = *(const float4*)(Xb + (size_t)r * DDIM + 4 * l);
            u64 hp, lp; split4(v, hp, lp);
            *(u64*)(smc + OFF_XH + r * ROWB + 8 * l) = hp;
            *(u64*)(smc + OFF_XL + r * ROWB + 8 * l) = lp;
            float ss = v.x*v.x + v.y*v.y + v.z*v.z + v.w*v.w;
            ss += __shfl_xor_sync(~0u, ss, 16); ss += __shfl_xor_sync(~0u, ss, 8);
            ss += __shfl_xor_sync(~0u, ss, 4);  ss += __shfl_xor_sync(~0u, ss, 2);
            ss += __shfl_xor_sync(~0u, ss, 1);
            if (l == 0) X2s[r] = ss;
        }
        __syncthreads();

        // ---- GEMM1: D = X·C^T, fused split sweep ----
        // per s: load xh/xl once; per tp: load ch/cl once; 6 MMAs per (s,tp).
        float dacc[16][4];
        #pragma unroll
        for (int i = 0; i < 16; ++i)
            #pragma unroll
            for (int j = 0; j < 4; ++j) dacc[i][j] = 0.f;

        {
            uint32_t abh = sb + OFF_XH + a1off;
            uint32_t abl = sb + OFF_XL + a1off;
            uint32_t cbh = sb + OFF_CH + b1off;
            uint32_t cbl = sb + OFF_CL + b1off;
            #pragma unroll 1
            for (int s = 0; s < 8; ++s) {
                uint32_t xh0, xh1, xh2, xh3, xl0, xl1, xl2, xl3;
                ldsm4(xh0, xh1, xh2, xh3, abh + 32u * s);
                ldsm4(xl0, xl1, xl2, xl3, abl + 32u * s);
                #pragma unroll
                for (int tp = 0; tp < 8; ++tp) {
                    uint32_t c0, c1, c2, c3;
                    ldsm4(c0, c1, c2, c3, cbh + (uint32_t)tp * (16u * ROWB) + 32u * s);
                    mma16816(dacc[2 * tp],     xh0, xh1, xh2, xh3, c0, c1);
                    mma16816(dacc[2 * tp + 1], xh0, xh1, xh2, xh3, c2, c3);
                    mma16816(dacc[2 * tp],     xl0, xl1, xl2, xl3, c0, c1);
                    mma16816(dacc[2 * tp + 1], xl0, xl1, xl2, xl3, c2, c3);
                    ldsm4(c0, c1, c2, c3, cbl + (uint32_t)tp * (16u * ROWB) + 32u * s);
                    mma16816(dacc[2 * tp],     xh0, xh1, xh2, xh3, c0, c1);
                    mma16816(dacc[2 * tp + 1], xh0, xh1, xh2, xh3, c2, c3);
                }
            }
        }

        // ---- softmax in register layout ----
        {
            int row0 = 16 * w + g;
            float x20 = X2s[row0], x21 = X2s[row0 + 8];
            float m0 = -3.4e38f, m1 = -3.4e38f;
            #pragma unroll
            for (int ti = 0; ti < 16; ++ti) {
                int k = 8 * ti + 2 * tq;
                float s0 = Ssm[k], s1 = Ssm[k + 1];
                float c20 = C2s[k], c21 = C2s[k + 1];
                dacc[ti][0] = s0 * (x20 + c20 - 2.f * dacc[ti][0]);
                dacc[ti][1] = s1 * (x20 + c21 - 2.f * dacc[ti][1]);
                dacc[ti][2] = s0 * (x21 + c20 - 2.f * dacc[ti][2]);
                dacc[ti][3] = s1 * (x21 + c21 - 2.f * dacc[ti][3]);
                m0 = fmaxf(m0, fmaxf(dacc[ti][0], dacc[ti][1]));
                m1 = fmaxf(m1, fmaxf(dacc[ti][2], dacc[ti][3]));
            }
            m0 = fmaxf(m0, __shfl_xor_sync(~0u, m0, 1));
            m0 = fmaxf(m0, __shfl_xor_sync(~0u, m0, 2));
            m1 = fmaxf(m1, __shfl_xor_sync(~0u, m1, 1));
            m1 = fmaxf(m1, __shfl_xor_sync(~0u, m1, 2));
            float sm0 = 0.f, sm1 = 0.f;
            #pragma unroll
            for (int ti = 0; ti < 16; ++ti) {
                dacc[ti][0] = __expf(dacc[ti][0] - m0);
                dacc[ti][1] = __expf(dacc[ti][1] - m0);
                dacc[ti][2] = __expf(dacc[ti][2] - m1);
                dacc[ti][3] = __expf(dacc[ti][3] - m1);
                sm0 += dacc[ti][0] + dacc[ti][1];
                sm1 += dacc[ti][2] + dacc[ti][3];
            }
            sm0 += __shfl_xor_sync(~0u, sm0, 1);
            sm0 += __shfl_xor_sync(~0u, sm0, 2);
            sm1 += __shfl_xor_sync(~0u, sm1, 1);
            sm1 += __shfl_xor_sync(~0u, sm1, 2);
            float inv0 = __frcp_rn(sm0), inv1 = __frcp_rn(sm1);

            // A hi/lo STS + Asum partials (reduced per-ti to cap registers)
            uint32_t arow0 = (uint32_t)row0 * ROWB + 4u * tq;
            uint32_t arow1 = arow0 + 8u * ROWB;
            float* aw = AW + w * 128;
            #pragma unroll
            for (int ti = 0; ti < 16; ++ti) {
                float a00 = dacc[ti][0] * inv0, a01 = dacc[ti][1] * inv0;
                float a10 = dacc[ti][2] * inv1, a11 = dacc[ti][3] * inv1;
                __nv_bfloat16 h00 = __float2bfloat16_rn(a00), h01 = __float2bfloat16_rn(a01);
                __nv_bfloat16 h10 = __float2bfloat16_rn(a10), h11 = __float2bfloat16_rn(a11);
                float f00 = __bfloat162float(h00), f01 = __bfloat162float(h01);
                float f10 = __bfloat162float(h10), f11 = __bfloat162float(h11);
                __nv_bfloat16 g00 = __float2bfloat16_rn(a00 - f00);
                __nv_bfloat16 g01 = __float2bfloat16_rn(a01 - f01);
                __nv_bfloat16 g10 = __float2bfloat16_rn(a10 - f10);
                __nv_bfloat16 g11 = __float2bfloat16_rn(a11 - f11);
                uint32_t hi0 = (uint32_t)__bfloat16_as_ushort(h00) | ((uint32_t)__bfloat16_as_ushort(h01) << 16);
                uint32_t hi1 = (uint32_t)__bfloat16_as_ushort(h10) | ((uint32_t)__bfloat16_as_ushort(h11) << 16);
                uint32_t lo0 = (uint32_t)__bfloat16_as_ushort(g00) | ((uint32_t)__bfloat16_as_ushort(g01) << 16);
                uint32_t lo1 = (uint32_t)__bfloat16_as_ushort(g10) | ((uint32_t)__bfloat16_as_ushort(g11) << 16);
                uint32_t cb2 = 16u * ti;
                *(uint32_t*)(smc + OFF_AH + arow0 + cb2) = hi0;
                *(uint32_t*)(smc + OFF_AH + arow1 + cb2) = hi1;
                *(uint32_t*)(smc + OFF_AL + arow0 + cb2) = lo0;
                *(uint32_t*)(smc + OFF_AL + arow1 + cb2) = lo1;
                // asum partial for cols 8ti+2tq, +1 (effective A = hi+lo)
                float av0 = (f00 + __bfloat162float(g00)) + (f10 + __bfloat162float(g10));
                float av1 = (f01 + __bfloat162float(g01)) + (f11 + __bfloat162float(g11));
                av0 += __shfl_xor_sync(~0u, av0, 4);
                av0 += __shfl_xor_sync(~0u, av0, 8);
                av0 += __shfl_xor_sync(~0u, av0, 16);
                av1 += __shfl_xor_sync(~0u, av1, 4);
                av1 += __shfl_xor_sync(~0u, av1, 8);
                av1 += __shfl_xor_sync(~0u, av1, 16);
                if (l < 4) {
                    aw[8 * ti + 2 * tq]     += av0;
                    aw[8 * ti + 2 * tq + 1] += av1;
                }
            }
        }
        __syncthreads();   // A tiles complete

        // ---- GEMM2: E += A^T·X, fused split sweep (trans frags) ----
        // per s: load ah/al once; per tp: load xh/xl once; 6 MMAs per (s,tp).
        {
            uint32_t abh = sb + OFF_AH + a2off;
            uint32_t abl = sb + OFF_AL + a2off;
            uint32_t xbh = sb + OFF_XH + b2off;
            uint32_t xbl = sb + OFF_XL + b2off;
            #pragma unroll 1
            for (int s = 0; s < 8; ++s) {
                uint32_t srow = (uint32_t)s * (16u * ROWB);
                uint32_t ah0, ah1, ah2, ah3, al0, al1, al2, al3;
                ldsm4t(ah0, ah1, ah2, ah3, abh + srow);
                ldsm4t(al0, al1, al2, al3, abl + srow);
                #pragma unroll
                for (int tp = 0; tp < 8; ++tp) {
                    uint32_t b0, b1, b2, b3;
                    ldsm4t(b0, b1, b2, b3, xbh + srow + 32u * tp);
                    mma16816(Eacc[2 * tp],     ah0, ah1, ah2, ah3, b0, b1);
                    mma16816(Eacc[2 * tp + 1], ah0, ah1, ah2, ah3, b2, b3);
                    mma16816(Eacc[2 * tp],     al0, al1, al2, al3, b0, b1);
                    mma16816(Eacc[2 * tp + 1], al0, al1, al2, al3, b2, b3);
                    ldsm4t(b0, b1, b2, b3, xbl + srow + 32u * tp);
                    mma16816(Eacc[2 * tp],     ah0, ah1, ah2, ah3, b0, b1);
                    mma16816(Eacc[2 * tp + 1], ah0, ah1, ah2, ah3, b2, b3);
                }
            }
        }
    }
}

extern "C" void kernel_launch(void* const* d_in, const int* in_sizes, int n_in,
                              void* d_out, int out_size) {
    (void)n_in;
    const float* X = (const float*)d_in[0];
    const float* C = (const float*)d_in[1];
    const float* S = (const float*)d_in[2];
    float* out = (float*)d_out;

    int b = out_size / (KDIM * DDIM);
    if (b < 1) b = 1;
    long long rows = (long long)in_sizes[0] / DDIM;
    int n = (int)(rows / b);

    cudaFuncSetAttribute(vq_encode_kernel,
                         cudaFuncAttributeMaxDynamicSharedMemorySize, SMEM_BYTES);

    int zgrid = (out_size + THREADS - 1) / THREADS;
    vq_zero_kernel<<<zgrid, THREADS>>>(out, out_size);
    vq_encode_kernel<<<GRID, THREADS, SMEM_BYTES>>>(X, C, S, out, n, b);
}